// round 1
// baseline (speedup 1.0000x reference)
#include <cuda_runtime.h>
#include <math.h>

// Problem constants (fixed by the reference)
#define NATOMS     8192
#define MAX_PAIRS  (64 * 8192)     // 524288
#define CUT2       25.0f           // cutoff_upper^2; cutoff_lower = 0 (always satisfied)

#define ROWS_PER_BLOCK 8           // one warp per row i
#define THREADS        256
#define TILE           2048        // j-positions cached in shared per step (32KB float4)

// Scratch (no allocations allowed -> device globals)
__device__ int g_counts[NATOMS];
__device__ int g_offsets[NATOMS];

// d2 with the SAME rounding as the reference: products rounded, then ((a+b)+c).
// __fmul_rn / __fadd_rn block fma contraction.
__device__ __forceinline__ float d2_exact(float dx, float dy, float dz) {
    float a = __fmul_rn(dx, dx);
    float b = __fmul_rn(dy, dy);
    float c = __fmul_rn(dz, dz);
    return __fadd_rn(__fadd_rn(a, b), c);
}

// ---------------------------------------------------------------------------
// Kernel 1: fill output with defaults.
// Layout (floats): [0,MP) = edge_index row0 (i), [MP,2MP) = row1 (j),
//                  [2MP,3MP) = edge_weight, [3MP,6MP) = edge_vec (row-major [MP,3])
// Invalid slots: index = -1, weight = 0, vec = 0.
// ---------------------------------------------------------------------------
__global__ void fill_kernel(float* __restrict__ out) {
    long long idx = (long long)blockIdx.x * blockDim.x + threadIdx.x;
    const long long total = 6LL * MAX_PAIRS;
    if (idx < total) {
        out[idx] = (idx < 2LL * MAX_PAIRS) ? -1.0f : 0.0f;
    }
}

// ---------------------------------------------------------------------------
// Kernel 2: per-row neighbor counts. One warp per row i; shared tile of
// (x,y,z,batch) packed as float4 so each pair eval is one LDS.128.
// ---------------------------------------------------------------------------
__global__ void count_kernel(const float* __restrict__ pos,
                             const int*   __restrict__ batch) {
    __shared__ float4 sp[TILE];
    const int warp = threadIdx.x >> 5;
    const int lane = threadIdx.x & 31;
    const int i = blockIdx.x * ROWS_PER_BLOCK + warp;

    const float pix = pos[3 * i + 0];
    const float piy = pos[3 * i + 1];
    const float piz = pos[3 * i + 2];
    const int   bi  = batch[i];

    int cnt = 0;
    for (int t = 0; t < NATOMS; t += TILE) {
        __syncthreads();
        for (int k = threadIdx.x; k < TILE; k += THREADS) {
            const int j = t + k;
            sp[k] = make_float4(pos[3 * j + 0], pos[3 * j + 1], pos[3 * j + 2],
                                __int_as_float(batch[j]));
        }
        __syncthreads();
        #pragma unroll 8
        for (int k = lane; k < TILE; k += 32) {
            const int j = t + k;
            const float4 pj = sp[k];
            const float dx = pix - pj.x;
            const float dy = piy - pj.y;
            const float dz = piz - pj.z;
            const float d2 = d2_exact(dx, dy, dz);
            const bool hit = (j != i) && (d2 < CUT2) && (__float_as_int(pj.w) == bi);
            cnt += hit ? 1 : 0;
        }
    }
    cnt = __reduce_add_sync(0xffffffffu, cnt);
    if (lane == 0) g_counts[i] = cnt;
}

// ---------------------------------------------------------------------------
// Kernel 3: exclusive prefix sum over 8192 counts. Single block, 256 threads,
// each thread owns 32 contiguous counts; Hillis-Steele over 256 partials.
// ---------------------------------------------------------------------------
__global__ void scan_kernel() {
    __shared__ int s[256];
    const int t = threadIdx.x;

    int local[32];
    int sum = 0;
    #pragma unroll
    for (int k = 0; k < 32; k++) {
        local[k] = g_counts[t * 32 + k];
        sum += local[k];
    }
    s[t] = sum;
    __syncthreads();

    // inclusive scan on 256 partials
    #pragma unroll
    for (int d = 1; d < 256; d <<= 1) {
        int v = (t >= d) ? s[t - d] : 0;
        __syncthreads();
        s[t] += v;
        __syncthreads();
    }
    int off = s[t] - sum;   // exclusive prefix for this thread's chunk

    #pragma unroll
    for (int k = 0; k < 32; k++) {
        g_offsets[t * 32 + k] = off;
        off += local[k];
    }
}

// ---------------------------------------------------------------------------
// Kernel 4: ordered write. Same tiling as count; within each warp the hits are
// compacted in ascending-j order via ballot rank, rows ordered by g_offsets.
// ---------------------------------------------------------------------------
__global__ void write_kernel(const float* __restrict__ pos,
                             const int*   __restrict__ batch,
                             float*       __restrict__ out) {
    __shared__ float4 sp[TILE];
    const int warp = threadIdx.x >> 5;
    const int lane = threadIdx.x & 31;
    const int i = blockIdx.x * ROWS_PER_BLOCK + warp;

    const float pix = pos[3 * i + 0];
    const float piy = pos[3 * i + 1];
    const float piz = pos[3 * i + 2];
    const int   bi  = batch[i];
    const float fi  = (float)i;

    int base = g_offsets[i];

    float* __restrict__ outI = out;
    float* __restrict__ outJ = out + MAX_PAIRS;
    float* __restrict__ outW = out + 2 * MAX_PAIRS;
    float* __restrict__ outV = out + 3 * MAX_PAIRS;

    const unsigned lt_mask = (1u << lane) - 1u;

    for (int t = 0; t < NATOMS; t += TILE) {
        __syncthreads();
        for (int k = threadIdx.x; k < TILE; k += THREADS) {
            const int j = t + k;
            sp[k] = make_float4(pos[3 * j + 0], pos[3 * j + 1], pos[3 * j + 2],
                                __int_as_float(batch[j]));
        }
        __syncthreads();
        for (int k = lane; k < TILE; k += 32) {
            const int j = t + k;
            const float4 pj = sp[k];
            const float dx = pix - pj.x;
            const float dy = piy - pj.y;
            const float dz = piz - pj.z;
            const float d2 = d2_exact(dx, dy, dz);
            const bool hit = (j != i) && (d2 < CUT2) && (__float_as_int(pj.w) == bi);

            const unsigned m = __ballot_sync(0xffffffffu, hit);
            if (hit) {
                const int p = base + __popc(m & lt_mask);
                if (p < MAX_PAIRS) {
                    outI[p] = fi;
                    outJ[p] = (float)j;
                    outW[p] = sqrtf(d2);
                    outV[3 * p + 0] = dx;
                    outV[3 * p + 1] = dy;
                    outV[3 * p + 2] = dz;
                }
            }
            base += __popc(m);
        }
    }
}

// ---------------------------------------------------------------------------
extern "C" void kernel_launch(void* const* d_in, const int* in_sizes, int n_in,
                              void* d_out, int out_size) {
    const float* pos   = (const float*)d_in[0];   // [8192, 3] f32
    const int*   batch = (const int*)d_in[1];     // [8192] i32
    float* out = (float*)d_out;                   // 6 * MAX_PAIRS floats

    (void)in_sizes; (void)n_in; (void)out_size;

    const long long total = 6LL * MAX_PAIRS;
    fill_kernel<<<(int)((total + 255) / 256), 256>>>(out);
    count_kernel<<<NATOMS / ROWS_PER_BLOCK, THREADS>>>(pos, batch);
    scan_kernel<<<1, 256>>>();
    write_kernel<<<NATOMS / ROWS_PER_BLOCK, THREADS>>>(pos, batch, out);
}

// round 2
// speedup vs baseline: 3.0691x; 3.0691x over previous
#include <cuda_runtime.h>
#include <math.h>

// Problem constants (fixed by the reference)
#define NATOMS     8192
#define MAX_PAIRS  (64 * 8192)     // 524288
#define CUT2       25.0f           // cutoff_upper^2; cutoff_lower = 0
#define NCELL1     9               // 45.0 / 5.0
#define NCELLS     (NCELL1 * NCELL1 * NCELL1)   // 729
#define MASK_WORDS 256             // 8192 bits per row

// Scratch (no allocations allowed -> device globals)
__device__ int      g_cell_count[NCELLS];
__device__ int      g_cell_off[NCELLS + 1];
__device__ int      g_cell_cursor[NCELLS];
__device__ float4   g_cell_pos[NATOMS];     // (x, y, z, atom_idx bits)
__device__ int      g_cell_batch[NATOMS];
__device__ unsigned g_mask[NATOMS * MASK_WORDS];  // 8 MB hit bitmask
__device__ int      g_counts[NATOMS];
__device__ int      g_offsets[NATOMS];

// d2 with the SAME rounding as the reference: rounded products, then ((a+b)+c).
__device__ __forceinline__ float d2_exact(float dx, float dy, float dz) {
    float a = __fmul_rn(dx, dx);
    float b = __fmul_rn(dy, dy);
    float c = __fmul_rn(dz, dz);
    return __fadd_rn(__fadd_rn(a, b), c);
}

__device__ __forceinline__ int cell_coord(float p) {
    int c = (int)(p * 0.2f);
    return c < 0 ? 0 : (c > NCELL1 - 1 ? NCELL1 - 1 : c);
}

// ---------------------------------------------------------------------------
// Kernel 1: fill output with defaults (vectorized float4).
// Layout (floats): [0,MP)=i, [MP,2MP)=j, [2MP,3MP)=weight, [3MP,6MP)=vec.
// ---------------------------------------------------------------------------
__global__ void fill_kernel(float4* __restrict__ out4) {
    const int total4 = (6 * MAX_PAIRS) / 4;          // 786432
    const int idx4   = (2 * MAX_PAIRS) / 4;          // 262144 (index region)
    int idx = blockIdx.x * blockDim.x + threadIdx.x;
    if (idx < total4) {
        float v = (idx < idx4) ? -1.0f : 0.0f;
        out4[idx] = make_float4(v, v, v, v);
    }
}

// ---------------------------------------------------------------------------
// Kernel 2: zero cell histogram.
// ---------------------------------------------------------------------------
__global__ void zero_kernel() {
    int t = threadIdx.x;
    if (t < NCELLS) g_cell_count[t] = 0;
}

// ---------------------------------------------------------------------------
// Kernel 3: histogram atoms into cells.
// ---------------------------------------------------------------------------
__global__ void hist_kernel(const float* __restrict__ pos) {
    int i = blockIdx.x * blockDim.x + threadIdx.x;
    if (i < NATOMS) {
        int cx = cell_coord(pos[3 * i + 0]);
        int cy = cell_coord(pos[3 * i + 1]);
        int cz = cell_coord(pos[3 * i + 2]);
        atomicAdd(&g_cell_count[cx * 81 + cy * 9 + cz], 1);
    }
}

// ---------------------------------------------------------------------------
// Kernel 4: exclusive scan over 729 cell counts (1 block, 1024 threads).
// ---------------------------------------------------------------------------
__global__ void cellscan_kernel() {
    __shared__ int s[1024];
    int t = threadIdx.x;
    int v = (t < NCELLS) ? g_cell_count[t] : 0;
    s[t] = v;
    __syncthreads();
    #pragma unroll
    for (int d = 1; d < 1024; d <<= 1) {
        int u = (t >= d) ? s[t - d] : 0;
        __syncthreads();
        s[t] += u;
        __syncthreads();
    }
    if (t < NCELLS) {
        int excl = s[t] - v;
        g_cell_off[t]    = excl;
        g_cell_cursor[t] = excl;
        if (t == NCELLS - 1) g_cell_off[NCELLS] = s[t];
    }
}

// ---------------------------------------------------------------------------
// Kernel 5: scatter atoms into cell-sorted arrays (packed float4 + batch).
// ---------------------------------------------------------------------------
__global__ void scatter_kernel(const float* __restrict__ pos,
                               const int*   __restrict__ batch) {
    int i = blockIdx.x * blockDim.x + threadIdx.x;
    if (i < NATOMS) {
        float x = pos[3 * i + 0], y = pos[3 * i + 1], z = pos[3 * i + 2];
        int c = cell_coord(x) * 81 + cell_coord(y) * 9 + cell_coord(z);
        int slot = atomicAdd(&g_cell_cursor[c], 1);
        g_cell_pos[slot]   = make_float4(x, y, z, __int_as_float(i));
        g_cell_batch[slot] = batch[i];
    }
}

// ---------------------------------------------------------------------------
// Kernel 6: count + bitmask. One warp per row i. Only neighbor-cell
// candidates are tested; hits set bits in a shared row bitmask (order-
// independent), which is then flushed to g_mask and popc'd into g_counts.
// z-adjacent cells are contiguous in cell id -> 9 coalesced ranges.
// ---------------------------------------------------------------------------
__global__ void count_kernel(const float* __restrict__ pos,
                             const int*   __restrict__ batch) {
    __shared__ unsigned smask[8][MASK_WORDS];
    const int warp = threadIdx.x >> 5;
    const int lane = threadIdx.x & 31;
    const int i = blockIdx.x * 8 + warp;

    for (int k = lane; k < MASK_WORDS; k += 32) smask[warp][k] = 0;
    __syncwarp();

    const float pix = pos[3 * i + 0];
    const float piy = pos[3 * i + 1];
    const float piz = pos[3 * i + 2];
    const int   bi  = batch[i];

    const int cx = cell_coord(pix), cy = cell_coord(piy), cz = cell_coord(piz);
    const int x0 = max(cx - 1, 0), x1 = min(cx + 1, NCELL1 - 1);
    const int y0 = max(cy - 1, 0), y1 = min(cy + 1, NCELL1 - 1);
    const int z0 = max(cz - 1, 0), z1 = min(cz + 1, NCELL1 - 1);

    for (int ix = x0; ix <= x1; ix++) {
        for (int iy = y0; iy <= y1; iy++) {
            const int cbase = ix * 81 + iy * 9;
            const int s = g_cell_off[cbase + z0];
            const int e = g_cell_off[cbase + z1 + 1];
            for (int t = s + lane; t < e; t += 32) {
                const float4 pj = g_cell_pos[t];
                const float dx = pix - pj.x;
                const float dy = piy - pj.y;
                const float dz = piz - pj.z;
                const float d2 = d2_exact(dx, dy, dz);
                const int j = __float_as_int(pj.w);
                if (d2 < CUT2 && j != i) {
                    if (g_cell_batch[t] == bi) {
                        atomicOr(&smask[warp][j >> 5], 1u << (j & 31));
                    }
                }
            }
        }
    }
    __syncwarp();

    int cnt = 0;
    unsigned* mrow = &g_mask[(size_t)i * MASK_WORDS];
    for (int k = lane; k < MASK_WORDS; k += 32) {
        unsigned w = smask[warp][k];
        mrow[k] = w;
        cnt += __popc(w);
    }
    cnt = __reduce_add_sync(0xffffffffu, cnt);
    if (lane == 0) g_counts[i] = cnt;
}

// ---------------------------------------------------------------------------
// Kernel 7: exclusive prefix sum over 8192 row counts.
// ---------------------------------------------------------------------------
__global__ void rowscan_kernel() {
    __shared__ int s[256];
    const int t = threadIdx.x;

    int local[32];
    int sum = 0;
    #pragma unroll
    for (int k = 0; k < 32; k++) {
        local[k] = g_counts[t * 32 + k];
        sum += local[k];
    }
    s[t] = sum;
    __syncthreads();
    #pragma unroll
    for (int d = 1; d < 256; d <<= 1) {
        int v = (t >= d) ? s[t - d] : 0;
        __syncthreads();
        s[t] += v;
        __syncthreads();
    }
    int off = s[t] - sum;
    #pragma unroll
    for (int k = 0; k < 32; k++) {
        g_offsets[t * 32 + k] = off;
        off += local[k];
    }
}

// ---------------------------------------------------------------------------
// Kernel 8: ordered write from the bitmask. One warp per row; lane l owns
// words [8l, 8l+8) = j in [256l, 256l+256), so lane-rank scan + in-lane
// ascending bit extraction reproduces exact row-major (i, ascending-j) order.
// ---------------------------------------------------------------------------
__global__ void write_kernel(const float* __restrict__ pos,
                             float*       __restrict__ out) {
    const int warp = threadIdx.x >> 5;
    const int lane = threadIdx.x & 31;
    const int i = blockIdx.x * 8 + warp;

    const unsigned* mrow = &g_mask[(size_t)i * MASK_WORDS];
    const uint4* mrow4 = reinterpret_cast<const uint4*>(mrow) + lane * 2;
    uint4 a = mrow4[0];
    uint4 b = mrow4[1];
    unsigned w8[8] = {a.x, a.y, a.z, a.w, b.x, b.y, b.z, b.w};

    int myc = 0;
    #pragma unroll
    for (int t = 0; t < 8; t++) myc += __popc(w8[t]);

    // warp exclusive scan of myc
    int incl = myc;
    #pragma unroll
    for (int d = 1; d < 32; d <<= 1) {
        int v = __shfl_up_sync(0xffffffffu, incl, d);
        if (lane >= d) incl += v;
    }
    int p = g_offsets[i] + incl - myc;

    const float pix = pos[3 * i + 0];
    const float piy = pos[3 * i + 1];
    const float piz = pos[3 * i + 2];
    const float fi  = (float)i;

    float* __restrict__ outI = out;
    float* __restrict__ outJ = out + MAX_PAIRS;
    float* __restrict__ outW = out + 2 * MAX_PAIRS;
    float* __restrict__ outV = out + 3 * MAX_PAIRS;

    #pragma unroll
    for (int t = 0; t < 8; t++) {
        unsigned word = w8[t];
        const int jbase = (lane * 8 + t) * 32;
        while (word) {
            const int bpos = __ffs(word) - 1;
            word &= word - 1;
            const int j = jbase + bpos;
            const float dx = pix - pos[3 * j + 0];
            const float dy = piy - pos[3 * j + 1];
            const float dz = piz - pos[3 * j + 2];
            const float d2 = d2_exact(dx, dy, dz);
            if (p < MAX_PAIRS) {
                outI[p] = fi;
                outJ[p] = (float)j;
                outW[p] = sqrtf(d2);
                outV[3 * p + 0] = dx;
                outV[3 * p + 1] = dy;
                outV[3 * p + 2] = dz;
            }
            p++;
        }
    }
}

// ---------------------------------------------------------------------------
extern "C" void kernel_launch(void* const* d_in, const int* in_sizes, int n_in,
                              void* d_out, int out_size) {
    const float* pos   = (const float*)d_in[0];   // [8192, 3] f32
    const int*   batch = (const int*)d_in[1];     // [8192] i32
    float* out = (float*)d_out;                   // 6 * MAX_PAIRS floats

    (void)in_sizes; (void)n_in; (void)out_size;

    const int total4 = (6 * MAX_PAIRS) / 4;
    fill_kernel<<<(total4 + 255) / 256, 256>>>((float4*)out);
    zero_kernel<<<1, 1024>>>();
    hist_kernel<<<NATOMS / 256, 256>>>(pos);
    cellscan_kernel<<<1, 1024>>>();
    scatter_kernel<<<NATOMS / 256, 256>>>(pos, batch);
    count_kernel<<<NATOMS / 8, 256>>>(pos, batch);
    rowscan_kernel<<<1, 256>>>();
    write_kernel<<<NATOMS / 8, 256>>>(pos, out);
}

// round 3
// speedup vs baseline: 3.2232x; 1.0502x over previous
#include <cuda_runtime.h>
#include <math.h>

// Problem constants (fixed by the reference)
#define NATOMS     8192
#define MAX_PAIRS  (64 * 8192)     // 524288
#define CUT2       25.0f           // cutoff_upper^2; cutoff_lower = 0
#define NCELL1     9               // 45.0 / 5.0
#define NCELLS     (NCELL1 * NCELL1 * NCELL1)   // 729
#define MASK_WORDS 256             // 8192 bits per row
#define NBLOCKS    (NATOMS / 8)    // 1024 blocks, 8 rows (warps) each
#define FULLMASK   0xffffffffu

// Scratch (no allocations allowed -> device globals)
__device__ int      g_cell_off[NCELLS + 1];
__device__ float4   g_cell_pos[NATOMS];      // (x, y, z, atom_idx bits)
__device__ int      g_cell_batch[NATOMS];
__device__ unsigned g_state[NBLOCKS];        // decoupled-lookback state
__device__ int      g_total;

// d2 with the SAME rounding as the reference: rounded products, then ((a+b)+c).
__device__ __forceinline__ float d2_exact(float dx, float dy, float dz) {
    float a = __fmul_rn(dx, dx);
    float b = __fmul_rn(dy, dy);
    float c = __fmul_rn(dz, dz);
    return __fadd_rn(__fadd_rn(a, b), c);
}

__device__ __forceinline__ int cell_coord(float p) {
    int c = (int)(p * 0.2f);
    return c < 0 ? 0 : (c > NCELL1 - 1 ? NCELL1 - 1 : c);
}

// ---------------------------------------------------------------------------
// Kernel 1: full cell-list build in ONE block (1024 threads, 8 atoms/thread):
// shared histogram -> warp-shuffle hierarchical scan -> shared-cursor scatter.
// Also zeros the lookback state for kernel 2.
// ---------------------------------------------------------------------------
__global__ void cellbuild_kernel(const float* __restrict__ pos,
                                 const int*   __restrict__ batch) {
    __shared__ int hist[NCELLS];
    __shared__ int cursor[NCELLS];
    __shared__ int wsum[32];
    const int tid  = threadIdx.x;
    const int lane = tid & 31;
    const int warp = tid >> 5;

    g_state[tid] = 0;                         // reset lookback state (1024)
    for (int k = tid; k < NCELLS; k += 1024) hist[k] = 0;
    __syncthreads();

    int   mycell[8];
    float mx[8], my[8], mz[8];
    #pragma unroll
    for (int a = 0; a < 8; a++) {
        const int i = tid + a * 1024;
        const float x = pos[3 * i + 0];
        const float y = pos[3 * i + 1];
        const float z = pos[3 * i + 2];
        mx[a] = x; my[a] = y; mz[a] = z;
        const int c = cell_coord(x) * 81 + cell_coord(y) * 9 + cell_coord(z);
        mycell[a] = c;
        atomicAdd(&hist[c], 1);
    }
    __syncthreads();

    // exclusive scan over 729 counts: warp shuffles + 32-wide top scan
    const int v = (tid < NCELLS) ? hist[tid] : 0;
    int incl = v;
    #pragma unroll
    for (int d = 1; d < 32; d <<= 1) {
        int u = __shfl_up_sync(FULLMASK, incl, d);
        if (lane >= d) incl += u;
    }
    if (lane == 31) wsum[warp] = incl;
    __syncthreads();
    if (warp == 0) {
        int s = wsum[lane];
        int si = s;
        #pragma unroll
        for (int d = 1; d < 32; d <<= 1) {
            int u = __shfl_up_sync(FULLMASK, si, d);
            if (lane >= d) si += u;
        }
        wsum[lane] = si - s;                  // exclusive warp offsets
    }
    __syncthreads();
    const int excl = incl - v + wsum[warp];
    if (tid < NCELLS) {
        g_cell_off[tid] = excl;
        cursor[tid] = excl;
        if (tid == NCELLS - 1) g_cell_off[NCELLS] = excl + v;
    }
    __syncthreads();

    #pragma unroll
    for (int a = 0; a < 8; a++) {
        const int i = tid + a * 1024;
        const int slot = atomicAdd(&cursor[mycell[a]], 1);
        g_cell_pos[slot]   = make_float4(mx[a], my[a], mz[a], __int_as_float(i));
        g_cell_batch[slot] = batch[i];
    }
}

// ---------------------------------------------------------------------------
// Kernel 2: fused count + global scan (decoupled lookback) + ordered write.
// One warp per row i, 8 rows per block. Row bitmasks live ONLY in shared.
// Output order = exact row-major (i, ascending j), matching the reference.
// ---------------------------------------------------------------------------
__global__ void pairs_kernel(const float* __restrict__ pos,
                             const int*   __restrict__ batch,
                             float*       __restrict__ out) {
    __shared__ unsigned smask[8][MASK_WORDS];
    __shared__ int scnt[8];
    __shared__ int srowoff[8];
    const int warp = threadIdx.x >> 5;
    const int lane = threadIdx.x & 31;
    const int b = blockIdx.x;
    const int i = b * 8 + warp;

    for (int k = lane; k < MASK_WORDS; k += 32) smask[warp][k] = 0;

    const float pix = pos[3 * i + 0];
    const float piy = pos[3 * i + 1];
    const float piz = pos[3 * i + 2];
    const int   bi  = batch[i];
    __syncwarp();

    const int cx = cell_coord(pix), cy = cell_coord(piy), cz = cell_coord(piz);
    const int x0 = max(cx - 1, 0), x1 = min(cx + 1, NCELL1 - 1);
    const int y0 = max(cy - 1, 0), y1 = min(cy + 1, NCELL1 - 1);
    const int z0 = max(cz - 1, 0), z1 = min(cz + 1, NCELL1 - 1);

    for (int ix = x0; ix <= x1; ix++) {
        for (int iy = y0; iy <= y1; iy++) {
            const int cbase = ix * 81 + iy * 9;
            const int s = g_cell_off[cbase + z0];
            const int e = g_cell_off[cbase + z1 + 1];
            for (int t = s + lane; t < e; t += 32) {
                const float4 pj = g_cell_pos[t];
                const float dx = pix - pj.x;
                const float dy = piy - pj.y;
                const float dz = piz - pj.z;
                const float d2 = d2_exact(dx, dy, dz);
                const int j = __float_as_int(pj.w);
                if (d2 < CUT2 && j != i) {
                    if (g_cell_batch[t] == bi) {
                        atomicOr(&smask[warp][j >> 5], 1u << (j & 31));
                    }
                }
            }
        }
    }
    __syncwarp();

    // per-row count from the mask
    int cnt = 0;
    for (int k = lane; k < MASK_WORDS; k += 32) cnt += __popc(smask[warp][k]);
    cnt = __reduce_add_sync(FULLMASK, cnt);
    if (lane == 0) scnt[warp] = cnt;
    __syncthreads();

    // warp 0: publish aggregate, decoupled lookback, publish inclusive prefix
    if (warp == 0) {
        int agg = 0;
        if (lane == 0) {
            #pragma unroll
            for (int r = 0; r < 8; r++) agg += scnt[r];
            atomicExch(&g_state[b], (1u << 30) | (unsigned)agg);
        }
        agg = __shfl_sync(FULLMASK, agg, 0);

        int excl = 0;
        int look = b - 1;
        bool done = (look < 0);
        while (!done) {
            const int idx = look - lane;
            unsigned v;
            if (idx >= 0) {
                do { v = *(volatile unsigned*)&g_state[idx]; } while (v == 0u);
            } else {
                v = (2u << 30);               // virtual PREFIX=0 before block 0
            }
            const unsigned flag = v >> 30;
            const int val = (int)(v & 0x3FFFFFFFu);
            const unsigned pmask = __ballot_sync(FULLMASK, flag == 2u);
            const int firstP = __ffs(pmask) - 1;       // closest predecessor w/ prefix
            const int limit = (pmask != 0u) ? firstP : 31;
            int contrib = (lane <= limit) ? val : 0;
            #pragma unroll
            for (int d = 16; d > 0; d >>= 1)
                contrib += __shfl_down_sync(FULLMASK, contrib, d);
            contrib = __shfl_sync(FULLMASK, contrib, 0);
            excl += contrib;
            if (pmask != 0u) done = true; else look -= 32;
        }
        if (lane == 0) {
            atomicExch(&g_state[b], (2u << 30) | (unsigned)(excl + agg));
            if (b == NBLOCKS - 1) g_total = excl + agg;
            int run = excl;
            #pragma unroll
            for (int r = 0; r < 8; r++) { srowoff[r] = run; run += scnt[r]; }
        }
    }
    __syncthreads();

    // ordered write: lane l owns words [8l, 8l+8) -> j in [256l, 256(l+1))
    unsigned w8[8];
    #pragma unroll
    for (int t = 0; t < 8; t++) w8[t] = smask[warp][lane * 8 + t];

    int myc = 0;
    #pragma unroll
    for (int t = 0; t < 8; t++) myc += __popc(w8[t]);

    int incl = myc;
    #pragma unroll
    for (int d = 1; d < 32; d <<= 1) {
        int u = __shfl_up_sync(FULLMASK, incl, d);
        if (lane >= d) incl += u;
    }
    int p = srowoff[warp] + incl - myc;

    const float fi = (float)i;
    float* __restrict__ outI = out;
    float* __restrict__ outJ = out + MAX_PAIRS;
    float* __restrict__ outW = out + 2 * MAX_PAIRS;
    float* __restrict__ outV = out + 3 * MAX_PAIRS;

    #pragma unroll
    for (int t = 0; t < 8; t++) {
        unsigned word = w8[t];
        const int jbase = (lane * 8 + t) * 32;
        while (word) {
            const int bpos = __ffs(word) - 1;
            word &= word - 1;
            const int j = jbase + bpos;
            const float dx = pix - pos[3 * j + 0];
            const float dy = piy - pos[3 * j + 1];
            const float dz = piz - pos[3 * j + 2];
            const float d2 = d2_exact(dx, dy, dz);
            if (p < MAX_PAIRS) {
                outI[p] = fi;
                outJ[p] = (float)j;
                outW[p] = sqrtf(d2);
                outV[3 * p + 0] = dx;
                outV[3 * p + 1] = dy;
                outV[3 * p + 2] = dz;
            }
            p++;
        }
    }
}

// ---------------------------------------------------------------------------
// Kernel 3: fill only the INVALID tail [total, MAX_PAIRS) with defaults.
// index -> -1, weight -> 0, vec -> 0. Runs after pairs_kernel.
// ---------------------------------------------------------------------------
__global__ void filltail_kernel(float* __restrict__ out) {
    int total = g_total;
    if (total > MAX_PAIRS) total = MAX_PAIRS;
    const long long MP = MAX_PAIRS;
    const long long e = (long long)blockIdx.x * blockDim.x + threadIdx.x;
    if (e >= 6 * MP) return;
    if (e < 2 * MP) {                                   // edge_index (i then j)
        if ((int)(e >= MP ? e - MP : e) >= total) out[e] = -1.0f;
    } else if (e < 3 * MP) {                            // edge_weight
        if ((int)(e - 2 * MP) >= total) out[e] = 0.0f;
    } else {                                            // edge_vec [MP,3]
        if ((e - 3 * MP) >= 3LL * total) out[e] = 0.0f;
    }
}

// ---------------------------------------------------------------------------
extern "C" void kernel_launch(void* const* d_in, const int* in_sizes, int n_in,
                              void* d_out, int out_size) {
    const float* pos   = (const float*)d_in[0];   // [8192, 3] f32
    const int*   batch = (const int*)d_in[1];     // [8192] i32
    float* out = (float*)d_out;                   // 6 * MAX_PAIRS floats

    (void)in_sizes; (void)n_in; (void)out_size;

    cellbuild_kernel<<<1, 1024>>>(pos, batch);
    pairs_kernel<<<NBLOCKS, 256>>>(pos, batch, out);
    const long long total = 6LL * MAX_PAIRS;
    filltail_kernel<<<(int)((total + 511) / 512), 512>>>(out);
}